// round 10
// baseline (speedup 1.0000x reference)
#include <cuda_runtime.h>
#include <cuda_bf16.h>
#include <cstdint>
#include <math.h>

#define N_BATCH 4096
#define D_FEAT  64
#define KDIM    256                       // packed [u, -2mu, a, b]
#define TILE    128
#define NBLK    (N_BATCH / TILE)          // 32
#define NPAIRS  (NBLK * (NBLK + 1) / 2)   // 528
#define NCHUNK  8                         // k chunks of 32
#define STAGES  3
#define NTHR    256

// ---- scratch (static device globals; no allocation allowed) ----
// bf16 fragment-permuted operands for mma.sync.m16n8k16
// A: [blk 32][chunk 8][rb 8][ks 2][lane 32][slot 4][half 2] bf16
__device__ __align__(256) __nv_bfloat16 g_VA[N_BATCH * KDIM];
// B (k rotated by 128): [blk 32][chunk 8][nb 16][lane 32][slot 4][half 2] bf16
__device__ __align__(256) __nv_bfloat16 g_VB[N_BATCH * KDIM];
__device__ __align__(256) float g_C[N_BATCH];
__device__ __align__(256) float g_P[N_BATCH];
__device__ __align__(256) float g_RP[N_BATCH];
__device__ double g_acc[2];
__device__ unsigned g_done;
__device__ unsigned g_ready[NBLK];        // per-block precompute flags

// ---- smem: 3 stages x 16KB (A 8KB + B 8KB) + mbarriers; epilogue reuses stage 0 ----
#define STAGE_BYTES 16384
#define MB_BASE   (STAGES * STAGE_BYTES)   // 49152
#define SM_BYTES  (MB_BASE + 64)
#define OFF_ROWD 0      // 128 float4 (bytes 0..2048)
#define OFF_COLD 2048
#define OFF_REDP 4096
#define OFF_REDN 4136

// ---------------------------------------------------------------
__device__ __forceinline__ uint32_t smem_u32(const void* p) {
    uint32_t a;
    asm("{ .reg .u64 t; cvta.to.shared.u64 t, %1; cvt.u32.u64 %0, t; }" : "=r"(a) : "l"(p));
    return a;
}
__device__ __forceinline__ void cp16(uint32_t dst, const void* src) {
    asm volatile("cp.async.cg.shared.global [%0], [%1], 16;" :: "r"(dst), "l"(src));
}
#define MB_INIT(mb, c)  asm volatile("mbarrier.init.shared.b64 [%0], %1;" :: "r"(mb), "r"((uint32_t)(c)) : "memory")
#define MB_ARRIVE(mb)   asm volatile("mbarrier.arrive.shared.b64 _, [%0];" :: "r"(mb) : "memory")
#define CP_MB_ARRIVE(mb) asm volatile("cp.async.mbarrier.arrive.noinc.shared.b64 [%0];" :: "r"(mb) : "memory")

__device__ __forceinline__ void mbwait(uint32_t mb, uint32_t phase) {
    asm volatile(
        "{\n\t.reg .pred P;\n\t"
        "LW_%=:\n\t"
        "mbarrier.try_wait.parity.shared.b64 P, [%0], %1;\n\t"
        "@!P bra LW_%=;\n\t}"
        :: "r"(mb), "r"(phase) : "memory");
}
__device__ __forceinline__ uint32_t mb_full(uint32_t smb, int s)  { return smb + MB_BASE + s * 16; }
__device__ __forceinline__ uint32_t mb_empty(uint32_t smb, int s) { return smb + MB_BASE + s * 16 + 8; }

__device__ __forceinline__ unsigned ld_acq(const unsigned* p) {
    unsigned v;
    asm volatile("ld.global.acquire.gpu.u32 %0, [%1];" : "=r"(v) : "l"(p) : "memory");
    return v;
}

// ---------------------------------------------------------------
// fragment-permuted bf16 store: value x at k=t, value y at k=128+t for `row`
__device__ __forceinline__ void store_pair(int row, int t, float x, float y) {
    int b = row >> 7, r = row & 127;
    int rb = r >> 4, ri = r & 15;
    int nb = r >> 3, ji = r & 7;
    __nv_bfloat16 vals[2] = { __float2bfloat16_rn(x), __float2bfloat16_rn(y) };
    int ks_[2] = { t, 128 + t };
    #pragma unroll
    for (int q = 0; q < 2; q++) {
        int k = ks_[q];
        int c  = k >> 5, kc = k & 31;
        int ks = kc >> 4, kk = kc & 15;
        int half = kk & 1;
        int cB = (c + 4) & 7;   // J-side rotation baked into B layout
        int laneA = (ri & 7) * 4 + ((kk >> 1) & 3);
        int slotA = (ri >> 3) + 2 * (kk >> 3);
        size_t offA = (((((size_t)b * 8 + c) * 8 + rb) * 2 + ks) * 32 + laneA) * 8 + slotA * 2 + half;
        g_VA[offA] = vals[q];
        int laneB = ji * 4 + ((kk >> 1) & 3);
        int slotB = ks * 2 + (kk >> 3);
        size_t offB = ((((size_t)b * 8 + cB) * 16 + nb) * 32 + laneB) * 8 + slotB * 2 + half;
        g_VB[offB] = vals[q];
    }
}

// ---------------------------------------------------------------
// One chunk = 16KB: A 8KB + B 8KB. 256 threads x 2 x cp16 = 16KB.
__device__ __forceinline__ void issue_chunk(uint32_t smbase, int stage,
                                            int bi, int bj, int c, int tid) {
    const __nv_bfloat16* srcA = g_VA + ((size_t)bi * 8 + c) * 4096;
    const __nv_bfloat16* srcB = g_VB + ((size_t)bj * 8 + c) * 4096;
    uint32_t dst = smbase + stage * STAGE_BYTES;
    #pragma unroll
    for (int it = 0; it < 2; it++) {
        int idx = tid + it * NTHR;
        cp16(dst + idx * 16,        srcA + idx * 8);
        cp16(dst + 8192 + idx * 16, srcB + idx * 8);
    }
}

// fragment loads (uint4 units within a stage)
__device__ __forceinline__ void lda(const uint4* pA, int wm, int ks, int lane,
                                    uint32_t a[4][4]) {
    #pragma unroll
    for (int tm = 0; tm < 4; tm++) {
        const uint4 v = pA[(((wm * 4 + tm) * 2 + ks) * 32 + lane)];
        a[tm][0] = v.x; a[tm][1] = v.y; a[tm][2] = v.z; a[tm][3] = v.w;
    }
}
__device__ __forceinline__ void ldb4(const uint4* pB, int wn, int lane,
                                     uint32_t b[4][4]) {
    #pragma unroll
    for (int tn = 0; tn < 4; tn++) {
        const uint4 v = pB[((wn * 4 + tn) * 32 + lane)];
        b[tn][0] = v.x; b[tn][1] = v.y; b[tn][2] = v.z; b[tn][3] = v.w;
    }
}

// contribution = 2*sigmoid(sym) = 1 + tanh(sym/2); R/C carry 0.125-folded constants
__device__ __forceinline__ void ep_elem(float S, float4 R, float4 C, int r, int cl,
                                        bool diag, float& pos, float& neg) {
    float hs = fmaf(0.125f, S, R.x) + fmaf(R.z, C.x, fmaf(R.y, C.y, C.z));
    float th;
    asm("tanh.approx.f32 %0, %1;" : "=f"(th) : "f"(hs));
    if (!diag || (r < cl)) {
        float t = 1.0f + th;
        if (__float_as_int(R.w) == __float_as_int(C.w)) pos += t; else neg += t;
    }
}

extern __shared__ __align__(16) float sm_dyn[];

__global__ void __launch_bounds__(NTHR, 2)
fused_kernel(const float* __restrict__ mu, const float* __restrict__ var,
             const int* __restrict__ labels, float* __restrict__ out) {
    float* sm = sm_dyn;
    uint32_t smb = smem_u32(sm);
    int tid  = threadIdx.x;
    int wid  = tid >> 5;
    int lane = tid & 31;

    // ================= producer CTAs: per-block precompute =================
    if (blockIdx.x < NBLK) {
        int b = blockIdx.x;
        if (b == 0 && tid == 0) { g_acc[0] = 0.0; g_acc[1] = 0.0; }
        // warp per row, 16 rows per warp
        for (int rr = 0; rr < 16; rr++) {
            int row = b * TILE + wid * 16 + rr;
            float v0 = var[row * D_FEAT + lane];
            float m0 = mu [row * D_FEAT + lane];
            float v1 = var[row * D_FEAT + lane + 32];
            float m1 = mu [row * D_FEAT + lane + 32];
            float iv0 = 1.0f / v0, iv1 = 1.0f / v1;
            store_pair(row, lane,      v0 + m0 * m0, iv0);
            store_pair(row, lane + 32, v1 + m1 * m1, iv1);
            store_pair(row, lane + 64, -2.0f * m0,   m0 * iv0);
            store_pair(row, lane + 96, -2.0f * m1,   m1 * iv1);
            float sc = m0 * m0 * iv0 + m1 * m1 * iv1;
            float sp = v0 * v1;
            #pragma unroll
            for (int off = 16; off; off >>= 1) {
                sc += __shfl_xor_sync(0xffffffffu, sc, off);
                sp *= __shfl_xor_sync(0xffffffffu, sp, off);
            }
            if (lane == 0) {
                g_C[row]  = sc;
                g_P[row]  = sp;
                g_RP[row] = 1.0f / (sp + 1e-8f);
            }
        }
        __syncthreads();
        __threadfence();
        if (tid == 0) atomicExch(&g_ready[b], 1u);
        return;
    }

    // ================= pair CTAs =================
    int wm = wid & 1;        // 64-row half
    int wn = wid >> 1;       // 32-col quarter

    int t = blockIdx.x - NBLK, bi = 0;
    while (t >= NBLK - bi) { t -= NBLK - bi; bi++; }
    int bj = bi + t;

    // ---- init mbarriers; wait for producer blocks {0, bi, bj} ----
    if (tid == 0) {
        #pragma unroll
        for (int s = 0; s < STAGES; s++) {
            MB_INIT(mb_full(smb, s), NTHR);
            MB_INIT(mb_empty(smb, s), NTHR);
        }
        while (ld_acq(&g_ready[0])  == 0) __nanosleep(64);
        while (ld_acq(&g_ready[bi]) == 0) __nanosleep(64);
        while (ld_acq(&g_ready[bj]) == 0) __nanosleep(64);
    }
    __syncthreads();

    float acc[4][4][4];
    #pragma unroll
    for (int i = 0; i < 4; i++)
        #pragma unroll
        for (int j = 0; j < 4; j++)
            #pragma unroll
            for (int k = 0; k < 4; k++) acc[i][j][k] = 0.0f;

    // prologue: issue chunks 0 and 1
    issue_chunk(smb, 0, bi, bj, 0, tid);
    CP_MB_ARRIVE(mb_full(smb, 0));
    issue_chunk(smb, 1, bi, bj, 1, tid);
    CP_MB_ARRIVE(mb_full(smb, 1));

    #pragma unroll
    for (int c = 0; c < NCHUNK; c++) {
        const int s = c % STAGES;
        if (c + 2 < NCHUNK) {
            const int c2 = c + 2, s2 = c2 % STAGES, k2 = c2 / STAGES;
            if (k2 > 0) mbwait(mb_empty(smb, s2), (uint32_t)((k2 - 1) & 1));
            issue_chunk(smb, s2, bi, bj, c2, tid);
            CP_MB_ARRIVE(mb_full(smb, s2));
        }
        mbwait(mb_full(smb, s), (uint32_t)((c / STAGES) & 1));

        const uint4* pA = (const uint4*)((const char*)sm + s * STAGE_BYTES);
        const uint4* pB = (const uint4*)((const char*)sm + s * STAGE_BYTES + 8192);
        uint32_t B[4][4];
        ldb4(pB, wn, lane, B);
        #pragma unroll
        for (int ks = 0; ks < 2; ks++) {
            uint32_t A[4][4];
            lda(pA, wm, ks, lane, A);
            #pragma unroll
            for (int tm = 0; tm < 4; tm++)
                #pragma unroll
                for (int tn = 0; tn < 4; tn++)
                    asm volatile(
                        "mma.sync.aligned.m16n8k16.row.col.f32.bf16.bf16.f32 "
                        "{%0,%1,%2,%3},{%4,%5,%6,%7},{%8,%9},{%0,%1,%2,%3};"
                        : "+f"(acc[tm][tn][0]), "+f"(acc[tm][tn][1]),
                          "+f"(acc[tm][tn][2]), "+f"(acc[tm][tn][3])
                        : "r"(A[tm][0]), "r"(A[tm][1]), "r"(A[tm][2]), "r"(A[tm][3]),
                          "r"(B[tn][ks * 2]), "r"(B[tn][ks * 2 + 1]));
        }
        MB_ARRIVE(mb_empty(smb, s));
    }

    // ---- epilogue (reuses stage-0 smem after full-block sync) ----
    __syncthreads();
    float4* rowd = (float4*)((char*)sm + OFF_ROWD);
    float4* cold = (float4*)((char*)sm + OFF_COLD);
    if (tid < 128) {
        int gi = bi * TILE + tid, gj = bj * TILE + tid;
        rowd[tid] = make_float4(0.125f * g_C[gi], g_P[gi], g_RP[gi],
                                __int_as_float(labels[gi]));
        cold[tid] = make_float4(0.125f * g_P[gj], 0.125f * g_RP[gj],
                                0.125f * g_C[gj] - 16.0f, __int_as_float(labels[gj]));
    }
    __syncthreads();

    bool diag = (bi == bj);
    float pos = 0.0f, neg = 0.0f;
    int r0 = wm * 64 + (lane >> 2);
    int c0 = wn * 32 + 2 * (lane & 3);
    #pragma unroll
    for (int tm = 0; tm < 4; tm++) {
        int r1 = r0 + tm * 16, r2 = r1 + 8;
        float4 R1 = rowd[r1], R2 = rowd[r2];
        #pragma unroll
        for (int tn = 0; tn < 4; tn++) {
            int ca = c0 + tn * 8;
            float4 C1 = cold[ca], C2 = cold[ca + 1];
            ep_elem(acc[tm][tn][0], R1, C1, r1, ca,     diag, pos, neg);
            ep_elem(acc[tm][tn][1], R1, C2, r1, ca + 1, diag, pos, neg);
            ep_elem(acc[tm][tn][2], R2, C1, r2, ca,     diag, pos, neg);
            ep_elem(acc[tm][tn][3], R2, C2, r2, ca + 1, diag, pos, neg);
        }
    }

    #pragma unroll
    for (int off = 16; off; off >>= 1) {
        pos += __shfl_xor_sync(0xffffffffu, pos, off);
        neg += __shfl_xor_sync(0xffffffffu, neg, off);
    }
    float* redp = (float*)((char*)sm + OFF_REDP);
    float* redn = (float*)((char*)sm + OFF_REDN);
    if (lane == 0) { redp[wid] = pos; redn[wid] = neg; }
    __syncthreads();
    if (tid == 0) {
        float p = 0.0f, n = 0.0f;
        #pragma unroll
        for (int i = 0; i < 8; i++) { p += redp[i]; n += redn[i]; }
        atomicAdd(&g_acc[0], (double)p);
        atomicAdd(&g_acc[1], (double)n);
        __threadfence();
        unsigned v = atomicAdd(&g_done, 1u);
        if (v == NPAIRS - 1) {               // last pair CTA finalizes
            g_done = 0;
            #pragma unroll
            for (int i = 0; i < NBLK; i++) g_ready[i] = 0;   // reset for next replay
            double P = g_acc[0], N = g_acc[1];
            const double invN2 = 1.0 / ((double)N_BATCH * (double)N_BATCH);
            out[0] = (float)(P * invN2);
            out[1] = (float)(N * invN2);
            out[2] = (float)P;
            out[3] = (float)N;
        }
    }
}

// ---------------------------------------------------------------
extern "C" void kernel_launch(void* const* d_in, const int* in_sizes, int n_in,
                              void* d_out, int out_size) {
    const float* mu     = (const float*)d_in[0];
    const float* var    = (const float*)d_in[1];
    const int*   labels = (const int*)d_in[2];
    float* out = (float*)d_out;

    cudaFuncSetAttribute(fused_kernel, cudaFuncAttributeMaxDynamicSharedMemorySize, SM_BYTES);

    fused_kernel<<<NPAIRS + NBLK, NTHR, SM_BYTES>>>(mu, var, labels, out);
}

// round 11
// speedup vs baseline: 1.1041x; 1.1041x over previous
#include <cuda_runtime.h>
#include <cuda_bf16.h>
#include <cstdint>
#include <math.h>

#define N_BATCH 4096
#define D_FEAT  64
#define KDIM    256                       // packed [u, -2mu, a, b]
#define TILE    128
#define NBLK    (N_BATCH / TILE)          // 32
#define NPAIRS  (NBLK * (NBLK + 1) / 2)   // 528
#define NCHUNK  8                         // k chunks of 32
#define STAGES  4
#define PFD     3                         // prefetch distance
#define NTHR    256

// ---- scratch (static device globals; no allocation allowed) ----
// bf16 fragment-permuted operands for mma.sync.m16n8k16
// A: [blk 32][chunk 8][rb 8][ks 2][lane 32][slot 4][half 2] bf16
__device__ __align__(256) __nv_bfloat16 g_VA[N_BATCH * KDIM];
// B (k rotated by 128): [blk 32][chunk 8][nb 16][lane 32][slot 4][half 2] bf16
__device__ __align__(256) __nv_bfloat16 g_VB[N_BATCH * KDIM];
__device__ __align__(256) float g_C[N_BATCH];
__device__ __align__(256) float g_P[N_BATCH];
__device__ __align__(256) float g_RP[N_BATCH];
__device__ double g_acc[2];
__device__ unsigned g_done;

// ---- smem: 4 stages x 16KB (A 8KB + B 8KB) + mbarriers; epilogue reuses stage 0 ----
#define STAGE_BYTES 16384
#define MB_BASE   (STAGES * STAGE_BYTES)   // 65536
#define SM_BYTES  (MB_BASE + 128)
#define OFF_ROWD 0      // 128 float4 (bytes 0..2048)
#define OFF_COLD 2048
#define OFF_REDP 4096
#define OFF_REDN 4136

// ---------------------------------------------------------------
__device__ __forceinline__ uint32_t smem_u32(const void* p) {
    uint32_t a;
    asm("{ .reg .u64 t; cvta.to.shared.u64 t, %1; cvt.u32.u64 %0, t; }" : "=r"(a) : "l"(p));
    return a;
}
__device__ __forceinline__ void cp16(uint32_t dst, const void* src) {
    asm volatile("cp.async.cg.shared.global [%0], [%1], 16;" :: "r"(dst), "l"(src));
}
#define MB_INIT(mb, c)  asm volatile("mbarrier.init.shared.b64 [%0], %1;" :: "r"(mb), "r"((uint32_t)(c)) : "memory")
#define MB_ARRIVE(mb)   asm volatile("mbarrier.arrive.shared.b64 _, [%0];" :: "r"(mb) : "memory")
#define CP_MB_ARRIVE(mb) asm volatile("cp.async.mbarrier.arrive.noinc.shared.b64 [%0];" :: "r"(mb) : "memory")

__device__ __forceinline__ void mbwait(uint32_t mb, uint32_t phase) {
    asm volatile(
        "{\n\t.reg .pred P;\n\t"
        "LW_%=:\n\t"
        "mbarrier.try_wait.parity.shared.b64 P, [%0], %1;\n\t"
        "@!P bra LW_%=;\n\t}"
        :: "r"(mb), "r"(phase) : "memory");
}
__device__ __forceinline__ uint32_t mb_full(uint32_t smb, int s)  { return smb + MB_BASE + s * 16; }
__device__ __forceinline__ uint32_t mb_empty(uint32_t smb, int s) { return smb + MB_BASE + s * 16 + 8; }

// ---------------------------------------------------------------
// 4096 blocks x 128 threads: bf16-round, write fragment-permuted operands
__global__ void precompute_kernel(const float* __restrict__ mu,
                                  const float* __restrict__ var) {
    int row = blockIdx.x;
    int tid = threadIdx.x;
    if (row == 0 && tid == 0) { g_acc[0] = 0.0; g_acc[1] = 0.0; }
    int d = tid & 63;
    float v  = var[row * D_FEAT + d];
    float m  = mu [row * D_FEAT + d];
    float iv = 1.0f / v;
    float x, y;
    if (tid < 64) { x = v + m * m;  y = iv; }      // k = tid, k = 128+tid
    else          { x = -2.0f * m;  y = m * iv; }
    __nv_bfloat16 vals[2] = { __float2bfloat16_rn(x), __float2bfloat16_rn(y) };

    int b = row >> 7, r = row & 127;
    int rb = r >> 4, ri = r & 15;
    int nb = r >> 3, ji = r & 7;
    int ks_[2] = { tid, 128 + tid };
    #pragma unroll
    for (int q = 0; q < 2; q++) {
        int k = ks_[q];
        int c  = k >> 5, kc = k & 31;
        int ks = kc >> 4, kk = kc & 15;
        int half = kk & 1;
        int cB = (c + 4) & 7;   // J-side rotation baked into B layout
        int laneA = (ri & 7) * 4 + ((kk >> 1) & 3);
        int slotA = (ri >> 3) + 2 * (kk >> 3);
        size_t offA = (((((size_t)b * 8 + c) * 8 + rb) * 2 + ks) * 32 + laneA) * 8 + slotA * 2 + half;
        g_VA[offA] = vals[q];
        int laneB = ji * 4 + ((kk >> 1) & 3);
        int slotB = ks * 2 + (kk >> 3);
        size_t offB = ((((size_t)b * 8 + cB) * 16 + nb) * 32 + laneB) * 8 + slotB * 2 + half;
        g_VB[offB] = vals[q];
    }

    __shared__ float sc[64];
    __shared__ float sp[64];
    if (tid < 64) { sc[tid] = m * m * iv; sp[tid] = v; }
    __syncthreads();
    #pragma unroll
    for (int s = 32; s > 0; s >>= 1) {
        if (tid < s) { sc[tid] += sc[tid + s]; sp[tid] *= sp[tid + s]; }
        __syncthreads();
    }
    if (tid == 0) {
        g_C[row]  = sc[0];
        g_P[row]  = sp[0];
        g_RP[row] = 1.0f / (sp[0] + 1e-8f);
    }
}

// ---------------------------------------------------------------
// One chunk = 16KB: A 8KB + B 8KB. 256 threads x 2 x cp16 = 16KB.
__device__ __forceinline__ void issue_chunk(uint32_t smbase, int stage,
                                            int bi, int bj, int c, int tid) {
    const __nv_bfloat16* srcA = g_VA + ((size_t)bi * 8 + c) * 4096;
    const __nv_bfloat16* srcB = g_VB + ((size_t)bj * 8 + c) * 4096;
    uint32_t dst = smbase + stage * STAGE_BYTES;
    #pragma unroll
    for (int it = 0; it < 2; it++) {
        int idx = tid + it * NTHR;
        cp16(dst + idx * 16,        srcA + idx * 8);
        cp16(dst + 8192 + idx * 16, srcB + idx * 8);
    }
}

// fragment loads (uint4 units within a stage)
__device__ __forceinline__ void lda(const uint4* pA, int wm, int ks, int lane,
                                    uint32_t a[4][4]) {
    #pragma unroll
    for (int tm = 0; tm < 4; tm++) {
        const uint4 v = pA[(((wm * 4 + tm) * 2 + ks) * 32 + lane)];
        a[tm][0] = v.x; a[tm][1] = v.y; a[tm][2] = v.z; a[tm][3] = v.w;
    }
}
__device__ __forceinline__ void ldb4(const uint4* pB, int wn, int lane,
                                     uint32_t b[4][4]) {
    #pragma unroll
    for (int tn = 0; tn < 4; tn++) {
        const uint4 v = pB[((wn * 4 + tn) * 32 + lane)];
        b[tn][0] = v.x; b[tn][1] = v.y; b[tn][2] = v.z; b[tn][3] = v.w;
    }
}

// contribution = 2*sigmoid(sym) = 1 + tanh(sym/2); R/C carry 0.125-folded constants
__device__ __forceinline__ void ep_elem(float S, float4 R, float4 C, int r, int cl,
                                        bool diag, float& pos, float& neg) {
    float hs = fmaf(0.125f, S, R.x) + fmaf(R.z, C.x, fmaf(R.y, C.y, C.z));
    float th;
    asm("tanh.approx.f32 %0, %1;" : "=f"(th) : "f"(hs));
    if (!diag || (r < cl)) {
        float t = 1.0f + th;
        if (__float_as_int(R.w) == __float_as_int(C.w)) pos += t; else neg += t;
    }
}

extern __shared__ __align__(16) float sm_dyn[];

__global__ void __launch_bounds__(NTHR, 2)
pair_kernel(const int* __restrict__ labels, float* __restrict__ out) {
    float* sm = sm_dyn;
    uint32_t smb = smem_u32(sm);
    int tid  = threadIdx.x;
    int wid  = tid >> 5;
    int lane = tid & 31;
    int wm = wid & 1;        // 64-row half
    int wn = wid >> 1;       // 32-col quarter

    int t = blockIdx.x, bi = 0;
    while (t >= NBLK - bi) { t -= NBLK - bi; bi++; }
    int bj = bi + t;

    float acc[4][4][4];
    #pragma unroll
    for (int i = 0; i < 4; i++)
        #pragma unroll
        for (int j = 0; j < 4; j++)
            #pragma unroll
            for (int k = 0; k < 4; k++) acc[i][j][k] = 0.0f;

    // ---- init mbarriers ----
    if (tid == 0) {
        #pragma unroll
        for (int s = 0; s < STAGES; s++) {
            MB_INIT(mb_full(smb, s), NTHR);
            MB_INIT(mb_empty(smb, s), NTHR);
        }
    }
    __syncthreads();

    // prologue: issue chunks 0..PFD-1
    #pragma unroll
    for (int c = 0; c < PFD; c++) {
        issue_chunk(smb, c, bi, bj, c, tid);
        CP_MB_ARRIVE(mb_full(smb, c));
    }

    #pragma unroll
    for (int c = 0; c < NCHUNK; c++) {
        const int s = c % STAGES;
        if (c + PFD < NCHUNK) {
            const int c2 = c + PFD, s2 = c2 % STAGES, k2 = c2 / STAGES;
            if (k2 > 0) mbwait(mb_empty(smb, s2), (uint32_t)((k2 - 1) & 1));
            issue_chunk(smb, s2, bi, bj, c2, tid);
            CP_MB_ARRIVE(mb_full(smb, s2));
        }
        mbwait(mb_full(smb, s), (uint32_t)((c / STAGES) & 1));

        const uint4* pA = (const uint4*)((const char*)sm + s * STAGE_BYTES);
        const uint4* pB = (const uint4*)((const char*)sm + s * STAGE_BYTES + 8192);
        uint32_t B[4][4];
        ldb4(pB, wn, lane, B);
        #pragma unroll
        for (int ks = 0; ks < 2; ks++) {
            uint32_t A[4][4];
            lda(pA, wm, ks, lane, A);
            #pragma unroll
            for (int tm = 0; tm < 4; tm++)
                #pragma unroll
                for (int tn = 0; tn < 4; tn++)
                    asm volatile(
                        "mma.sync.aligned.m16n8k16.row.col.f32.bf16.bf16.f32 "
                        "{%0,%1,%2,%3},{%4,%5,%6,%7},{%8,%9},{%0,%1,%2,%3};"
                        : "+f"(acc[tm][tn][0]), "+f"(acc[tm][tn][1]),
                          "+f"(acc[tm][tn][2]), "+f"(acc[tm][tn][3])
                        : "r"(A[tm][0]), "r"(A[tm][1]), "r"(A[tm][2]), "r"(A[tm][3]),
                          "r"(B[tn][ks * 2]), "r"(B[tn][ks * 2 + 1]));
        }
        MB_ARRIVE(mb_empty(smb, s));
    }

    // ---- epilogue (reuses stage-0 smem after full-block sync) ----
    __syncthreads();
    float4* rowd = (float4*)((char*)sm + OFF_ROWD);
    float4* cold = (float4*)((char*)sm + OFF_COLD);
    if (tid < 128) {
        int gi = bi * TILE + tid, gj = bj * TILE + tid;
        rowd[tid] = make_float4(0.125f * g_C[gi], g_P[gi], g_RP[gi],
                                __int_as_float(labels[gi]));
        cold[tid] = make_float4(0.125f * g_P[gj], 0.125f * g_RP[gj],
                                0.125f * g_C[gj] - 16.0f, __int_as_float(labels[gj]));
    }
    __syncthreads();

    bool diag = (bi == bj);
    float pos = 0.0f, neg = 0.0f;
    int r0 = wm * 64 + (lane >> 2);
    int c0 = wn * 32 + 2 * (lane & 3);
    #pragma unroll
    for (int tm = 0; tm < 4; tm++) {
        int r1 = r0 + tm * 16, r2 = r1 + 8;
        float4 R1 = rowd[r1], R2 = rowd[r2];
        #pragma unroll
        for (int tn = 0; tn < 4; tn++) {
            int ca = c0 + tn * 8;
            float4 C1 = cold[ca], C2 = cold[ca + 1];
            ep_elem(acc[tm][tn][0], R1, C1, r1, ca,     diag, pos, neg);
            ep_elem(acc[tm][tn][1], R1, C2, r1, ca + 1, diag, pos, neg);
            ep_elem(acc[tm][tn][2], R2, C1, r2, ca,     diag, pos, neg);
            ep_elem(acc[tm][tn][3], R2, C2, r2, ca + 1, diag, pos, neg);
        }
    }

    #pragma unroll
    for (int off = 16; off; off >>= 1) {
        pos += __shfl_xor_sync(0xffffffffu, pos, off);
        neg += __shfl_xor_sync(0xffffffffu, neg, off);
    }
    float* redp = (float*)((char*)sm + OFF_REDP);
    float* redn = (float*)((char*)sm + OFF_REDN);
    if (lane == 0) { redp[wid] = pos; redn[wid] = neg; }
    __syncthreads();
    if (tid == 0) {
        float p = 0.0f, n = 0.0f;
        #pragma unroll
        for (int i = 0; i < 8; i++) { p += redp[i]; n += redn[i]; }
        atomicAdd(&g_acc[0], (double)p);
        atomicAdd(&g_acc[1], (double)n);
        __threadfence();
        unsigned v = atomicAdd(&g_done, 1u);
        if (v == NPAIRS - 1) {               // last CTA finalizes
            g_done = 0;
            double P = g_acc[0], N = g_acc[1];
            const double invN2 = 1.0 / ((double)N_BATCH * (double)N_BATCH);
            out[0] = (float)(P * invN2);
            out[1] = (float)(N * invN2);
            out[2] = (float)P;
            out[3] = (float)N;
        }
    }
}

// ---------------------------------------------------------------
extern "C" void kernel_launch(void* const* d_in, const int* in_sizes, int n_in,
                              void* d_out, int out_size) {
    const float* mu     = (const float*)d_in[0];
    const float* var    = (const float*)d_in[1];
    const int*   labels = (const int*)d_in[2];
    float* out = (float*)d_out;

    cudaFuncSetAttribute(pair_kernel, cudaFuncAttributeMaxDynamicSharedMemorySize, SM_BYTES);

    precompute_kernel<<<N_BATCH, 128>>>(mu, var);
    pair_kernel<<<NPAIRS, NTHR, SM_BYTES>>>(labels, out);
}

// round 12
// speedup vs baseline: 1.1097x; 1.0050x over previous
#include <cuda_runtime.h>
#include <cuda_bf16.h>
#include <cstdint>
#include <math.h>

#define N_BATCH 4096
#define D_FEAT  64
#define KDIM    256                       // packed [u, -2mu, a, b]
#define NBLK    32                        // 128-row I blocks
#define NJ64    64                        // 64-col J blocks
#define NITEMS  1056                      // sum_{bi} (64 - 2*bi)
#define NCHUNK  8                         // k chunks of 32
#define STAGES  4
#define PFD     3
#define NTHR    256
#define GRID    296                       // 148 SMs x 2 CTAs, fully resident

// ---- scratch (static device globals; no allocation allowed) ----
// A: [blk 32][chunk 8][rb 8][ks 2][lane 32][slot 4][half 2] bf16
__device__ __align__(256) __nv_bfloat16 g_VA[N_BATCH * KDIM];
// B (k rotated by 128): [blk 32][chunk 8][nb 16][lane 32][slot 4][half 2] bf16
__device__ __align__(256) __nv_bfloat16 g_VB[N_BATCH * KDIM];
__device__ __align__(256) float g_C[N_BATCH];
__device__ __align__(256) float g_P[N_BATCH];
__device__ __align__(256) float g_RP[N_BATCH];
__device__ double g_acc[2];
__device__ unsigned g_sync;
__device__ unsigned g_next;
__device__ unsigned g_done;

// ---- smem layout ----
// stages: 4 x 12KB (A 8KB + B 4KB) = 49152
#define STAGE_BYTES 12288
#define OFF_ROWD 49152      // 128 float4
#define OFF_COLD 51200      // 64 float4
#define OFF_REDP 52224
#define OFF_REDN 52256
#define OFF_IDX  52288
#define MB_BASE  52304      // 8 mbarriers
#define SM_BYTES 52480

// ---------------------------------------------------------------
__device__ __forceinline__ uint32_t smem_u32(const void* p) {
    uint32_t a;
    asm("{ .reg .u64 t; cvta.to.shared.u64 t, %1; cvt.u32.u64 %0, t; }" : "=r"(a) : "l"(p));
    return a;
}
__device__ __forceinline__ void cp16(uint32_t dst, const void* src) {
    asm volatile("cp.async.cg.shared.global [%0], [%1], 16;" :: "r"(dst), "l"(src));
}
#define MB_INIT(mb, c)  asm volatile("mbarrier.init.shared.b64 [%0], %1;" :: "r"(mb), "r"((uint32_t)(c)) : "memory")
#define MB_ARRIVE(mb)   asm volatile("mbarrier.arrive.shared.b64 _, [%0];" :: "r"(mb) : "memory")
#define CP_MB_ARRIVE(mb) asm volatile("cp.async.mbarrier.arrive.noinc.shared.b64 [%0];" :: "r"(mb) : "memory")

__device__ __forceinline__ void mbwait(uint32_t mb, uint32_t phase) {
    asm volatile(
        "{\n\t.reg .pred P;\n\t"
        "LW_%=:\n\t"
        "mbarrier.try_wait.parity.shared.b64 P, [%0], %1;\n\t"
        "@!P bra LW_%=;\n\t}"
        :: "r"(mb), "r"(phase) : "memory");
}
__device__ __forceinline__ uint32_t mb_full(uint32_t smb, int s)  { return smb + MB_BASE + s * 16; }
__device__ __forceinline__ uint32_t mb_empty(uint32_t smb, int s) { return smb + MB_BASE + s * 16 + 8; }

__device__ __forceinline__ unsigned ld_acq(const unsigned* p) {
    unsigned v;
    asm volatile("ld.global.acquire.gpu.u32 %0, [%1];" : "=r"(v) : "l"(p) : "memory");
    return v;
}

// fragment-permuted bf16 store: value x at k=t, value y at k=128+t for `row`
__device__ __forceinline__ void store_pair(int row, int t, float x, float y) {
    int b = row >> 7, r = row & 127;
    int rb = r >> 4, ri = r & 15;
    int nb = r >> 3, ji = r & 7;
    __nv_bfloat16 vals[2] = { __float2bfloat16_rn(x), __float2bfloat16_rn(y) };
    int ks_[2] = { t, 128 + t };
    #pragma unroll
    for (int q = 0; q < 2; q++) {
        int k = ks_[q];
        int c  = k >> 5, kc = k & 31;
        int ks = kc >> 4, kk = kc & 15;
        int half = kk & 1;
        int cB = (c + 4) & 7;   // J-side rotation baked into B layout
        int laneA = (ri & 7) * 4 + ((kk >> 1) & 3);
        int slotA = (ri >> 3) + 2 * (kk >> 3);
        size_t offA = (((((size_t)b * 8 + c) * 8 + rb) * 2 + ks) * 32 + laneA) * 8 + slotA * 2 + half;
        g_VA[offA] = vals[q];
        int laneB = ji * 4 + ((kk >> 1) & 3);
        int slotB = ks * 2 + (kk >> 3);
        size_t offB = ((((size_t)b * 8 + cB) * 16 + nb) * 32 + laneB) * 8 + slotB * 2 + half;
        g_VB[offB] = vals[q];
    }
}

// One chunk = 12KB: A 8KB + B(half) 4KB
__device__ __forceinline__ void issue_chunk(uint32_t smbase, int stage,
                                            int bi, int bjblk, int jhalf, int c, int tid) {
    const __nv_bfloat16* srcA = g_VA + ((size_t)bi * 8 + c) * 4096;
    const __nv_bfloat16* srcB = g_VB + ((size_t)bjblk * 8 + c) * 4096 + jhalf * 2048;
    uint32_t dst = smbase + stage * STAGE_BYTES;
    cp16(dst + tid * 16,               srcA + (size_t)tid * 8);
    cp16(dst + (tid + 256) * 16,       srcA + (size_t)(tid + 256) * 8);
    cp16(dst + 8192 + tid * 16,        srcB + (size_t)tid * 8);
}

__device__ __forceinline__ void ep_elem(float S, float4 R, float4 C, int r, int cl,
                                        int delta, float& pos, float& neg) {
    float hs = fmaf(0.125f, S, R.x) + fmaf(R.z, C.x, fmaf(R.y, C.y, C.z));
    float th;
    asm("tanh.approx.f32 %0, %1;" : "=f"(th) : "f"(hs));
    if (r < cl + delta) {
        float t = 1.0f + th;
        if (__float_as_int(R.w) == __float_as_int(C.w)) pos += t; else neg += t;
    }
}

extern __shared__ __align__(16) float sm_dyn[];

__global__ void __launch_bounds__(NTHR, 2)
fused_kernel(const float* __restrict__ mu, const float* __restrict__ var,
             const int* __restrict__ labels, float* __restrict__ out) {
    float* sm = sm_dyn;
    uint32_t smb = smem_u32(sm);
    int tid  = threadIdx.x;
    int wid  = tid >> 5;
    int lane = tid & 31;
    int wm = wid & 1;        // 64-row half
    int wn = wid >> 1;       // 16-col quarter of the 64-col tile

    // ---- mbarrier init ----
    if (tid == 0) {
        #pragma unroll
        for (int s = 0; s < STAGES; s++) {
            MB_INIT(mb_full(smb, s), NTHR);
            MB_INIT(mb_empty(smb, s), NTHR);
        }
    }

    // ================= phase 1: cooperative precompute =================
    for (int row = blockIdx.x * 8 + wid; row < N_BATCH; row += GRID * 8) {
        float v0 = var[row * D_FEAT + lane];
        float m0 = mu [row * D_FEAT + lane];
        float v1 = var[row * D_FEAT + lane + 32];
        float m1 = mu [row * D_FEAT + lane + 32];
        float iv0 = 1.0f / v0, iv1 = 1.0f / v1;
        store_pair(row, lane,      v0 + m0 * m0, iv0);
        store_pair(row, lane + 32, v1 + m1 * m1, iv1);
        store_pair(row, lane + 64, -2.0f * m0,   m0 * iv0);
        store_pair(row, lane + 96, -2.0f * m1,   m1 * iv1);
        float sc = m0 * m0 * iv0 + m1 * m1 * iv1;
        float sp = v0 * v1;
        #pragma unroll
        for (int off = 16; off; off >>= 1) {
            sc += __shfl_xor_sync(0xffffffffu, sc, off);
            sp *= __shfl_xor_sync(0xffffffffu, sp, off);
        }
        if (lane == 0) {
            g_C[row]  = sc;
            g_P[row]  = sp;
            g_RP[row] = 1.0f / (sp + 1e-8f);
        }
    }
    if (blockIdx.x == 0 && tid == 0) { g_acc[0] = 0.0; g_acc[1] = 0.0; }
    __syncthreads();
    __threadfence();
    // ---- software grid barrier (all 296 CTAs resident) ----
    if (tid == 0) {
        atomicAdd(&g_sync, 1u);
        while (ld_acq(&g_sync) < GRID) __nanosleep(64);
    }
    __syncthreads();

    // ================= phase 2: work-steal 128x64 items =================
    float4* rowd = (float4*)((char*)sm + OFF_ROWD);
    float4* cold = (float4*)((char*)sm + OFF_COLD);
    float* redp = (float*)((char*)sm + OFF_REDP);
    float* redn = (float*)((char*)sm + OFF_REDN);
    int* sidx = (int*)((char*)sm + OFF_IDX);

    bool first = true;
    for (;;) {
        if (tid == 0) *sidx = (int)atomicAdd(&g_next, 1u);
        __syncthreads();
        int idx = *sidx;
        if (idx >= NITEMS) break;

        // decode (bi, j64) with j64 >= 2*bi
        int t = idx, bi = 0;
        while (t >= NJ64 - 2 * bi) { t -= NJ64 - 2 * bi; bi++; }
        int j64 = 2 * bi + t;
        int bjblk = j64 >> 1, jhalf = j64 & 1;
        int delta = j64 * 64 - bi * 128;

        // epilogue constants early (hidden under mainloop)
        if (tid < 128) {
            int gi = bi * 128 + tid;
            rowd[tid] = make_float4(0.125f * g_C[gi], g_P[gi], g_RP[gi],
                                    __int_as_float(labels[gi]));
        }
        if (tid < 64) {
            int gj = j64 * 64 + tid;
            cold[tid] = make_float4(0.125f * g_P[gj], 0.125f * g_RP[gj],
                                    0.125f * g_C[gj] - 16.0f, __int_as_float(labels[gj]));
        }

        float acc[4][2][4];
        #pragma unroll
        for (int i = 0; i < 4; i++)
            #pragma unroll
            for (int j = 0; j < 2; j++)
                #pragma unroll
                for (int k = 0; k < 4; k++) acc[i][j][k] = 0.0f;

        // prologue
        #pragma unroll
        for (int c = 0; c < PFD; c++) {
            if (!first) mbwait(mb_empty(smb, c), 1u);
            issue_chunk(smb, c, bi, bjblk, jhalf, c, tid);
            CP_MB_ARRIVE(mb_full(smb, c));
        }

        #pragma unroll
        for (int c = 0; c < NCHUNK; c++) {
            const int s = c % STAGES;
            if (c + PFD < NCHUNK) {
                const int c2 = c + PFD, s2 = c2 % STAGES;
                if (c2 >= STAGES) mbwait(mb_empty(smb, s2), 0u);
                issue_chunk(smb, s2, bi, bjblk, jhalf, c2, tid);
                CP_MB_ARRIVE(mb_full(smb, s2));
            }
            mbwait(mb_full(smb, s), (uint32_t)((c / STAGES) & 1));

            const uint4* pA = (const uint4*)((const char*)sm + s * STAGE_BYTES);
            const uint4* pB = (const uint4*)((const char*)sm + s * STAGE_BYTES + 8192);
            uint32_t B[2][4];
            #pragma unroll
            for (int tn = 0; tn < 2; tn++) {
                const uint4 v = pB[(wn * 2 + tn) * 32 + lane];
                B[tn][0] = v.x; B[tn][1] = v.y; B[tn][2] = v.z; B[tn][3] = v.w;
            }
            #pragma unroll
            for (int ks = 0; ks < 2; ks++) {
                uint32_t A[4][4];
                #pragma unroll
                for (int tm = 0; tm < 4; tm++) {
                    const uint4 v = pA[((wm * 4 + tm) * 2 + ks) * 32 + lane];
                    A[tm][0] = v.x; A[tm][1] = v.y; A[tm][2] = v.z; A[tm][3] = v.w;
                }
                #pragma unroll
                for (int tm = 0; tm < 4; tm++)
                    #pragma unroll
                    for (int tn = 0; tn < 2; tn++)
                        asm volatile(
                            "mma.sync.aligned.m16n8k16.row.col.f32.bf16.bf16.f32 "
                            "{%0,%1,%2,%3},{%4,%5,%6,%7},{%8,%9},{%0,%1,%2,%3};"
                            : "+f"(acc[tm][tn][0]), "+f"(acc[tm][tn][1]),
                              "+f"(acc[tm][tn][2]), "+f"(acc[tm][tn][3])
                            : "r"(A[tm][0]), "r"(A[tm][1]), "r"(A[tm][2]), "r"(A[tm][3]),
                              "r"(B[tn][ks * 2]), "r"(B[tn][ks * 2 + 1]));
            }
            MB_ARRIVE(mb_empty(smb, s));
        }

        // ---- epilogue ----
        __syncthreads();    // rowd/cold visible; mainloop done block-wide
        float pos = 0.0f, neg = 0.0f;
        int r0 = wm * 64 + (lane >> 2);
        int c0 = wn * 16 + 2 * (lane & 3);
        #pragma unroll
        for (int tm = 0; tm < 4; tm++) {
            int r1 = r0 + tm * 16, r2 = r1 + 8;
            float4 R1 = rowd[r1], R2 = rowd[r2];
            #pragma unroll
            for (int tn = 0; tn < 2; tn++) {
                int ca = c0 + tn * 8;
                float4 C1 = cold[ca], C2 = cold[ca + 1];
                ep_elem(acc[tm][tn][0], R1, C1, r1, ca,     delta, pos, neg);
                ep_elem(acc[tm][tn][1], R1, C2, r1, ca + 1, delta, pos, neg);
                ep_elem(acc[tm][tn][2], R2, C1, r2, ca,     delta, pos, neg);
                ep_elem(acc[tm][tn][3], R2, C2, r2, ca + 1, delta, pos, neg);
            }
        }
        #pragma unroll
        for (int off = 16; off; off >>= 1) {
            pos += __shfl_xor_sync(0xffffffffu, pos, off);
            neg += __shfl_xor_sync(0xffffffffu, neg, off);
        }
        if (lane == 0) { redp[wid] = pos; redn[wid] = neg; }
        __syncthreads();
        if (tid == 0) {
            float p = 0.0f, n = 0.0f;
            #pragma unroll
            for (int i = 0; i < 8; i++) { p += redp[i]; n += redn[i]; }
            atomicAdd(&g_acc[0], (double)p);
            atomicAdd(&g_acc[1], (double)n);
        }
        first = false;
    }

    // ---- finish: last CTA finalizes + resets for graph replay ----
    if (tid == 0) {
        __threadfence();
        unsigned v = atomicAdd(&g_done, 1u);
        if (v == GRID - 1) {
            double P = g_acc[0], N = g_acc[1];
            const double invN2 = 1.0 / ((double)N_BATCH * (double)N_BATCH);
            out[0] = (float)(P * invN2);
            out[1] = (float)(N * invN2);
            out[2] = (float)P;
            out[3] = (float)N;
            g_sync = 0; g_next = 0; g_done = 0;
        }
    }
}

// ---------------------------------------------------------------
extern "C" void kernel_launch(void* const* d_in, const int* in_sizes, int n_in,
                              void* d_out, int out_size) {
    const float* mu     = (const float*)d_in[0];
    const float* var    = (const float*)d_in[1];
    const int*   labels = (const int*)d_in[2];
    float* out = (float*)d_out;

    cudaFuncSetAttribute(fused_kernel, cudaFuncAttributeMaxDynamicSharedMemorySize, SM_BYTES);

    fused_kernel<<<GRID, NTHR, SM_BYTES>>>(mu, var, labels, out);
}

// round 13
// speedup vs baseline: 1.3007x; 1.1722x over previous
#include <cuda_runtime.h>
#include <cuda_bf16.h>
#include <cstdint>
#include <math.h>

#define N_BATCH 4096
#define D_FEAT  64
#define KDIM    256                       // packed [u, -2mu, a, b]
#define TILE    128
#define NBLK    (N_BATCH / TILE)          // 32
#define NPAIRS  (NBLK * (NBLK + 1) / 2)   // 528
#define NCHUNK  8                         // k chunks of 32
#define STAGES  3
#define PFD     2
#define NTHR    256

// ---- scratch (static device globals; no allocation allowed) ----
// bf16 fragment-permuted operands for mma.sync.m16n8k16
// A: [blk 32][chunk 8][rb 8][ks 2][lane 32][slot 4][half 2] bf16
__device__ __align__(256) __nv_bfloat16 g_VA[N_BATCH * KDIM];
// B (k rotated by 128): [blk 32][chunk 8][nb 16][lane 32][slot 4][half 2] bf16
__device__ __align__(256) __nv_bfloat16 g_VB[N_BATCH * KDIM];
__device__ __align__(256) float g_C[N_BATCH];
__device__ __align__(256) float g_P[N_BATCH];
__device__ __align__(256) float g_RP[N_BATCH];
__device__ double g_acc[2];
__device__ unsigned g_done;

// ---- smem: 3 stages x 16KB + mbarriers + dedicated epilogue region ----
#define STAGE_BYTES 16384
#define MB_BASE   (STAGES * STAGE_BYTES)   // 49152
#define OFF_ROWD  (MB_BASE + 64)           // 128 float4
#define OFF_COLD  (OFF_ROWD + 2048)        // 128 float4
#define OFF_REDP  (OFF_COLD + 2048)
#define OFF_REDN  (OFF_REDP + 40)
#define SM_BYTES  (OFF_REDN + 64)

// ---------------------------------------------------------------
__device__ __forceinline__ uint32_t smem_u32(const void* p) {
    uint32_t a;
    asm("{ .reg .u64 t; cvta.to.shared.u64 t, %1; cvt.u32.u64 %0, t; }" : "=r"(a) : "l"(p));
    return a;
}
__device__ __forceinline__ void cp16(uint32_t dst, const void* src) {
    asm volatile("cp.async.cg.shared.global [%0], [%1], 16;" :: "r"(dst), "l"(src));
}
#define MB_INIT(mb, c)  asm volatile("mbarrier.init.shared.b64 [%0], %1;" :: "r"(mb), "r"((uint32_t)(c)) : "memory")
#define MB_ARRIVE(mb)   asm volatile("mbarrier.arrive.shared.b64 _, [%0];" :: "r"(mb) : "memory")
#define CP_MB_ARRIVE(mb) asm volatile("cp.async.mbarrier.arrive.noinc.shared.b64 [%0];" :: "r"(mb) : "memory")

__device__ __forceinline__ void mbwait(uint32_t mb, uint32_t phase) {
    asm volatile(
        "{\n\t.reg .pred P;\n\t"
        "LW_%=:\n\t"
        "mbarrier.try_wait.parity.shared.b64 P, [%0], %1;\n\t"
        "@!P bra LW_%=;\n\t}"
        :: "r"(mb), "r"(phase) : "memory");
}
__device__ __forceinline__ uint32_t mb_full(uint32_t smb, int s)  { return smb + MB_BASE + s * 16; }
__device__ __forceinline__ uint32_t mb_empty(uint32_t smb, int s) { return smb + MB_BASE + s * 16 + 8; }

// ---------------------------------------------------------------
// Fat precompute: 512 CTAs x 256 threads, one warp per row.
// Each lane handles features d0=2*lane, d0+1 -> all stores are 32-bit words.
__device__ __forceinline__ uint32_t pack_bf162(float lo, float hi) {
    __nv_bfloat16 l = __float2bfloat16_rn(lo), h = __float2bfloat16_rn(hi);
    uint16_t lb, hb;
    memcpy(&lb, &l, 2); memcpy(&hb, &h, 2);
    return (uint32_t)lb | ((uint32_t)hb << 16);
}

__global__ void __launch_bounds__(256)
precompute_kernel(const float* __restrict__ mu, const float* __restrict__ var) {
    int tid = threadIdx.x;
    int wid = tid >> 5;
    int lane = tid & 31;
    int row = blockIdx.x * 8 + wid;          // 512*8 = 4096 exactly
    if (blockIdx.x == 0 && tid == 0) { g_acc[0] = 0.0; g_acc[1] = 0.0; }

    float2 vv = ((const float2*)var)[row * 32 + lane];
    float2 mv = ((const float2*)mu )[row * 32 + lane];
    float iv0 = 1.0f / vv.x, iv1 = 1.0f / vv.y;

    // group g: values at k = g*64 + 2*lane (+1)
    uint32_t wv[4];
    wv[0] = pack_bf162(vv.x + mv.x * mv.x, vv.y + mv.y * mv.y);  // u
    wv[1] = pack_bf162(-2.0f * mv.x,       -2.0f * mv.y);        // -2mu
    wv[2] = pack_bf162(iv0,                iv1);                 // a
    wv[3] = pack_bf162(mv.x * iv0,         mv.y * iv1);          // b

    int b = row >> 7, r = row & 127;
    int rb = r >> 4, ri = r & 15;
    int nb = r >> 3, ji = r & 7;
    uint32_t* VA = (uint32_t*)g_VA;
    uint32_t* VB = (uint32_t*)g_VB;
    #pragma unroll
    for (int g = 0; g < 4; g++) {
        int k0 = g * 64 + 2 * lane;          // even
        int c  = k0 >> 5, kc = k0 & 31;
        int ks = kc >> 4, kk = kc & 15;
        int cB = (c + 4) & 7;                // J-side rotation baked into B layout
        int laneA = (ri & 7) * 4 + ((kk >> 1) & 3);
        int slotA = (ri >> 3) + 2 * (kk >> 3);
        size_t wA = (((((size_t)b * 8 + c) * 8 + rb) * 2 + ks) * 32 + laneA) * 4 + slotA;
        VA[wA] = wv[g];
        int laneB = ji * 4 + ((kk >> 1) & 3);
        int slotB = ks * 2 + (kk >> 3);
        size_t wB = ((((size_t)b * 8 + cB) * 16 + nb) * 32 + laneB) * 4 + slotB;
        VB[wB] = wv[g];
    }

    float sc = mv.x * mv.x * iv0 + mv.y * mv.y * iv1;
    float sp = vv.x * vv.y;
    #pragma unroll
    for (int off = 16; off; off >>= 1) {
        sc += __shfl_xor_sync(0xffffffffu, sc, off);
        sp *= __shfl_xor_sync(0xffffffffu, sp, off);
    }
    if (lane == 0) {
        g_C[row]  = sc;
        g_P[row]  = sp;
        g_RP[row] = 1.0f / (sp + 1e-8f);
    }
}

// ---------------------------------------------------------------
// One chunk = 16KB: A 8KB + B 8KB. 256 threads x 2 x cp16 = 16KB.
__device__ __forceinline__ void issue_chunk(uint32_t smbase, int stage,
                                            int bi, int bj, int c, int tid) {
    const __nv_bfloat16* srcA = g_VA + ((size_t)bi * 8 + c) * 4096;
    const __nv_bfloat16* srcB = g_VB + ((size_t)bj * 8 + c) * 4096;
    uint32_t dst = smbase + stage * STAGE_BYTES;
    #pragma unroll
    for (int it = 0; it < 2; it++) {
        int idx = tid + it * NTHR;
        cp16(dst + idx * 16,        srcA + idx * 8);
        cp16(dst + 8192 + idx * 16, srcB + idx * 8);
    }
}

// fragment loads (uint4 units within a stage)
__device__ __forceinline__ void lda(const uint4* pA, int wm, int ks, int lane,
                                    uint32_t a[4][4]) {
    #pragma unroll
    for (int tm = 0; tm < 4; tm++) {
        const uint4 v = pA[(((wm * 4 + tm) * 2 + ks) * 32 + lane)];
        a[tm][0] = v.x; a[tm][1] = v.y; a[tm][2] = v.z; a[tm][3] = v.w;
    }
}
__device__ __forceinline__ void ldb4(const uint4* pB, int wn, int lane,
                                     uint32_t b[4][4]) {
    #pragma unroll
    for (int tn = 0; tn < 4; tn++) {
        const uint4 v = pB[((wn * 4 + tn) * 32 + lane)];
        b[tn][0] = v.x; b[tn][1] = v.y; b[tn][2] = v.z; b[tn][3] = v.w;
    }
}

// contribution = 2*sigmoid(sym) = 1 + tanh(sym/2); R/C carry 0.125-folded constants
__device__ __forceinline__ void ep_elem(float S, float4 R, float4 C, int r, int cl,
                                        bool diag, float& pos, float& neg) {
    float hs = fmaf(0.125f, S, R.x) + fmaf(R.z, C.x, fmaf(R.y, C.y, C.z));
    float th;
    asm("tanh.approx.f32 %0, %1;" : "=f"(th) : "f"(hs));
    if (!diag || (r < cl)) {
        float t = 1.0f + th;
        if (__float_as_int(R.w) == __float_as_int(C.w)) pos += t; else neg += t;
    }
}

extern __shared__ __align__(16) float sm_dyn[];

__global__ void __launch_bounds__(NTHR, 2)
pair_kernel(const int* __restrict__ labels, float* __restrict__ out) {
    float* sm = sm_dyn;
    uint32_t smb = smem_u32(sm);
    int tid  = threadIdx.x;
    int wid  = tid >> 5;
    int lane = tid & 31;
    int wm = wid & 1;        // 64-row half
    int wn = wid >> 1;       // 32-col quarter

    int t = blockIdx.x, bi = 0;
    while (t >= NBLK - bi) { t -= NBLK - bi; bi++; }
    int bj = bi + t;

    float acc[4][4][4];
    #pragma unroll
    for (int i = 0; i < 4; i++)
        #pragma unroll
        for (int j = 0; j < 4; j++)
            #pragma unroll
            for (int k = 0; k < 4; k++) acc[i][j][k] = 0.0f;

    // ---- init mbarriers ----
    if (tid == 0) {
        #pragma unroll
        for (int s = 0; s < STAGES; s++) {
            MB_INIT(mb_full(smb, s), NTHR);
            MB_INIT(mb_empty(smb, s), NTHR);
        }
    }
    __syncthreads();

    // epilogue constants into dedicated smem region, hidden under mainloop
    float4* rowd = (float4*)((char*)sm + OFF_ROWD);
    float4* cold = (float4*)((char*)sm + OFF_COLD);
    if (tid < 128) {
        int gi = bi * TILE + tid, gj = bj * TILE + tid;
        rowd[tid] = make_float4(0.125f * g_C[gi], g_P[gi], g_RP[gi],
                                __int_as_float(labels[gi]));
        cold[tid] = make_float4(0.125f * g_P[gj], 0.125f * g_RP[gj],
                                0.125f * g_C[gj] - 16.0f, __int_as_float(labels[gj]));
    }

    // prologue: issue chunks 0..PFD-1
    #pragma unroll
    for (int c = 0; c < PFD; c++) {
        issue_chunk(smb, c, bi, bj, c, tid);
        CP_MB_ARRIVE(mb_full(smb, c));
    }

    #pragma unroll
    for (int c = 0; c < NCHUNK; c++) {
        const int s = c % STAGES;
        if (c + PFD < NCHUNK) {
            const int c2 = c + PFD, s2 = c2 % STAGES, k2 = c2 / STAGES;
            if (k2 > 0) mbwait(mb_empty(smb, s2), (uint32_t)((k2 - 1) & 1));
            issue_chunk(smb, s2, bi, bj, c2, tid);
            CP_MB_ARRIVE(mb_full(smb, s2));
        }
        mbwait(mb_full(smb, s), (uint32_t)((c / STAGES) & 1));

        const uint4* pA = (const uint4*)((const char*)sm + s * STAGE_BYTES);
        const uint4* pB = (const uint4*)((const char*)sm + s * STAGE_BYTES + 8192);
        uint32_t B[4][4];
        ldb4(pB, wn, lane, B);
        #pragma unroll
        for (int ks = 0; ks < 2; ks++) {
            uint32_t A[4][4];
            lda(pA, wm, ks, lane, A);
            #pragma unroll
            for (int tm = 0; tm < 4; tm++)
                #pragma unroll
                for (int tn = 0; tn < 4; tn++)
                    asm volatile(
                        "mma.sync.aligned.m16n8k16.row.col.f32.bf16.bf16.f32 "
                        "{%0,%1,%2,%3},{%4,%5,%6,%7},{%8,%9},{%0,%1,%2,%3};"
                        : "+f"(acc[tm][tn][0]), "+f"(acc[tm][tn][1]),
                          "+f"(acc[tm][tn][2]), "+f"(acc[tm][tn][3])
                        : "r"(A[tm][0]), "r"(A[tm][1]), "r"(A[tm][2]), "r"(A[tm][3]),
                          "r"(B[tn][ks * 2]), "r"(B[tn][ks * 2 + 1]));
        }
        MB_ARRIVE(mb_empty(smb, s));
    }

    // ---- epilogue ----
    __syncthreads();
    bool diag = (bi == bj);
    float pos = 0.0f, neg = 0.0f;
    int r0 = wm * 64 + (lane >> 2);
    int c0 = wn * 32 + 2 * (lane & 3);
    #pragma unroll
    for (int tm = 0; tm < 4; tm++) {
        int r1 = r0 + tm * 16, r2 = r1 + 8;
        float4 R1 = rowd[r1], R2 = rowd[r2];
        #pragma unroll
        for (int tn = 0; tn < 4; tn++) {
            int ca = c0 + tn * 8;
            float4 C1 = cold[ca], C2 = cold[ca + 1];
            ep_elem(acc[tm][tn][0], R1, C1, r1, ca,     diag, pos, neg);
            ep_elem(acc[tm][tn][1], R1, C2, r1, ca + 1, diag, pos, neg);
            ep_elem(acc[tm][tn][2], R2, C1, r2, ca,     diag, pos, neg);
            ep_elem(acc[tm][tn][3], R2, C2, r2, ca + 1, diag, pos, neg);
        }
    }

    #pragma unroll
    for (int off = 16; off; off >>= 1) {
        pos += __shfl_xor_sync(0xffffffffu, pos, off);
        neg += __shfl_xor_sync(0xffffffffu, neg, off);
    }
    float* redp = (float*)((char*)sm + OFF_REDP);
    float* redn = (float*)((char*)sm + OFF_REDN);
    if (lane == 0) { redp[wid] = pos; redn[wid] = neg; }
    __syncthreads();
    if (tid == 0) {
        float p = 0.0f, n = 0.0f;
        #pragma unroll
        for (int i = 0; i < 8; i++) { p += redp[i]; n += redn[i]; }
        atomicAdd(&g_acc[0], (double)p);
        atomicAdd(&g_acc[1], (double)n);
        __threadfence();
        unsigned v = atomicAdd(&g_done, 1u);
        if (v == NPAIRS - 1) {               // last CTA finalizes
            g_done = 0;
            double P = g_acc[0], N = g_acc[1];
            const double invN2 = 1.0 / ((double)N_BATCH * (double)N_BATCH);
            out[0] = (float)(P * invN2);
            out[1] = (float)(N * invN2);
            out[2] = (float)P;
            out[3] = (float)N;
        }
    }
}

// ---------------------------------------------------------------
extern "C" void kernel_launch(void* const* d_in, const int* in_sizes, int n_in,
                              void* d_out, int out_size) {
    const float* mu     = (const float*)d_in[0];
    const float* var    = (const float*)d_in[1];
    const int*   labels = (const int*)d_in[2];
    float* out = (float*)d_out;

    cudaFuncSetAttribute(pair_kernel, cudaFuncAttributeMaxDynamicSharedMemorySize, SM_BYTES);

    precompute_kernel<<<512, 256>>>(mu, var);
    pair_kernel<<<NPAIRS, NTHR, SM_BYTES>>>(labels, out);
}